// round 1
// baseline (speedup 1.0000x reference)
#include <cuda_runtime.h>
#include <math.h>

// Problem constants (fixed by the reference)
#define Bsz   4096
#define INDIM 1024
#define Dm    512
#define Nn    8
#define Ss    128
#define HOPS  4
#define MAXT  72      // max token tiles per hop: 4096/64 + 8

// -------- device scratch (no allocations allowed) --------
__device__ float g_z[Bsz * Dm];        // z / ping buffer
__device__ float g_buf[Bsz * Dm];      // pong buffer
__device__ float g_symmean[Bsz * Ss];
__device__ int   g_prog[Bsz * HOPS];
__device__ int   g_order[HOPS][Bsz];
__device__ int   g_tileE[HOPS][MAXT];
__device__ int   g_tileS[HOPS][MAXT];
__device__ int   g_tileC[HOPS][MAXT];
__device__ int   g_numTiles[HOPS];

__device__ __forceinline__ float gelu_tanh(float x) {
    // JAX default gelu (approximate=True)
    float x3 = x * x * x;
    return 0.5f * x * (1.0f + tanhf(0.7978845608028654f * (x + 0.044715f * x3)));
}

#define MMA16()                                                                              \
    _Pragma("unroll")                                                                        \
    for (int kk = 0; kk < 16; kk++) {                                                        \
        float4 a = *reinterpret_cast<const float4*>(&As[kk][ty]);                            \
        float4 b = *reinterpret_cast<const float4*>(&Bs[kk][tx]);                            \
        acc[0][0] = fmaf(a.x, b.x, acc[0][0]); acc[0][1] = fmaf(a.x, b.y, acc[0][1]);        \
        acc[0][2] = fmaf(a.x, b.z, acc[0][2]); acc[0][3] = fmaf(a.x, b.w, acc[0][3]);        \
        acc[1][0] = fmaf(a.y, b.x, acc[1][0]); acc[1][1] = fmaf(a.y, b.y, acc[1][1]);        \
        acc[1][2] = fmaf(a.y, b.z, acc[1][2]); acc[1][3] = fmaf(a.y, b.w, acc[1][3]);        \
        acc[2][0] = fmaf(a.z, b.x, acc[2][0]); acc[2][1] = fmaf(a.z, b.y, acc[2][1]);        \
        acc[2][2] = fmaf(a.z, b.z, acc[2][2]); acc[2][3] = fmaf(a.z, b.w, acc[2][3]);        \
        acc[3][0] = fmaf(a.w, b.x, acc[3][0]); acc[3][1] = fmaf(a.w, b.y, acc[3][1]);        \
        acc[3][2] = fmaf(a.w, b.z, acc[3][2]); acc[3][3] = fmaf(a.w, b.w, acc[3][3]);        \
    }

// ================= GEMM 1: z = x @ W_in + b_in   [4096,1024]x[1024,512] ==============
__global__ __launch_bounds__(256) void gemm_z_kernel(
    const float* __restrict__ A, const float* __restrict__ W, const float* __restrict__ bias) {
    __shared__ __align__(16) float As[16][68];
    __shared__ __align__(16) float Bs[16][64];
    const int bm = blockIdx.x * 64, bn = blockIdx.y * 64;
    const int tid  = threadIdx.x;
    const int arow = tid >> 2,  akq = (tid & 3) * 4;
    const int brow = tid >> 4,  bnq = (tid & 15) * 4;
    const int ty   = (tid >> 4) * 4, tx = (tid & 15) * 4;
    float acc[4][4] = {};
    const float* aptr = A + (bm + arow) * INDIM + akq;
    for (int k0 = 0; k0 < INDIM; k0 += 16) {
        float4 av = *reinterpret_cast<const float4*>(aptr + k0);
        float4 bv = *reinterpret_cast<const float4*>(W + (k0 + brow) * Dm + bn + bnq);
        As[akq + 0][arow] = av.x; As[akq + 1][arow] = av.y;
        As[akq + 2][arow] = av.z; As[akq + 3][arow] = av.w;
        *reinterpret_cast<float4*>(&Bs[brow][bnq]) = bv;
        __syncthreads();
        MMA16();
        __syncthreads();
    }
#pragma unroll
    for (int i = 0; i < 4; i++)
#pragma unroll
        for (int j = 0; j < 4; j++)
            g_z[(bm + ty + i) * Dm + bn + tx + j] = acc[i][j] + bias[bn + tx + j];
}

// ========= GEMM 2: sym[b, n*128+s] = sum_d z[b,d] * sym_W[n,d,s]   (K=512) ==========
__global__ __launch_bounds__(256) void gemm_sym_kernel(
    const float* __restrict__ symW, float* __restrict__ symOut) {
    __shared__ __align__(16) float As[16][68];
    __shared__ __align__(16) float Bs[16][64];
    const int bm = blockIdx.x * 64, bn = blockIdx.y * 64;   // bn over 1024 cols
    const int n_id = bn >> 7, s0 = bn & 127;
    const int tid  = threadIdx.x;
    const int arow = tid >> 2,  akq = (tid & 3) * 4;
    const int brow = tid >> 4,  bnq = (tid & 15) * 4;
    const int ty   = (tid >> 4) * 4, tx = (tid & 15) * 4;
    float acc[4][4] = {};
    const float* aptr = g_z + (bm + arow) * Dm + akq;
    const float* bbase = symW + n_id * (Dm * Ss) + s0 + bnq;
    for (int k0 = 0; k0 < Dm; k0 += 16) {
        float4 av = *reinterpret_cast<const float4*>(aptr + k0);
        float4 bv = *reinterpret_cast<const float4*>(bbase + (k0 + brow) * Ss);
        As[akq + 0][arow] = av.x; As[akq + 1][arow] = av.y;
        As[akq + 2][arow] = av.z; As[akq + 3][arow] = av.w;
        *reinterpret_cast<float4*>(&Bs[brow][bnq]) = bv;
        __syncthreads();
        MMA16();
        __syncthreads();
    }
#pragma unroll
    for (int i = 0; i < 4; i++)
#pragma unroll
        for (int j = 0; j < 4; j++)
            symOut[(bm + ty + i) * (Nn * Ss) + bn + tx + j] = acc[i][j];
}

// ================== symmean[b,s] = mean_n sym[b,n,s] ==================
__global__ void mean_kernel(const float* __restrict__ symOut) {
    int i = blockIdx.x * blockDim.x + threadIdx.x;   // < 4096*128
    int b = i >> 7, s = i & 127;
    const float* p = symOut + b * (Nn * Ss) + s;
    float sum = 0.f;
#pragma unroll
    for (int n = 0; n < Nn; n++) sum += p[n * Ss];
    g_symmean[i] = sum * 0.125f;
}

// ====== router: logits (fp64 accumulation for argmax fidelity) + argmax -> prog ======
__global__ __launch_bounds__(288) void router_kernel(
    const float* __restrict__ RW, const float* __restrict__ rb, float* __restrict__ progf) {
    __shared__ float rin[8][640];
    __shared__ float lg[8][36];
    const int b0 = blockIdx.x * 8;
    const int tid = threadIdx.x;
    for (int i = tid; i < 8 * 640; i += 288) {
        int t = i / 640, k = i - t * 640;
        rin[t][k] = (k < Dm) ? g_z[(b0 + t) * Dm + k]
                             : g_symmean[(b0 + t) * Ss + (k - Dm)];
    }
    __syncthreads();
    {
        int t = tid / 36, j = tid - t * 36;
        double acc = (double)rb[j];
        for (int k = 0; k < 640; k++)
            acc += (double)rin[t][k] * (double)RW[k * 36 + j];
        lg[t][j] = (float)acc;
    }
    __syncthreads();
    if (tid < 32) {
        int t = tid >> 2, h = tid & 3;
        const float* l = &lg[t][h * 9];
        float best = l[0]; int bi = 0;
#pragma unroll
        for (int j = 1; j < 9; j++)
            if (l[j] > best) { best = l[j]; bi = j; }   // first-max tie-break, like jnp.argmax
        g_prog[(b0 + t) * HOPS + h] = bi;
        progf[(b0 + t) * HOPS + h] = (float)bi;
    }
}

// ======= schedule: group active tokens by (hop, expert); build 64-row tiles =======
__global__ void schedule_kernel() {
    __shared__ int cnt[HOPS][Nn];
    __shared__ int cur[HOPS][Nn];
    const int tid = threadIdx.x;
    if (tid < HOPS * Nn) cnt[tid / Nn][tid % Nn] = 0;
    __syncthreads();
    for (int b = tid; b < Bsz; b += blockDim.x) {
        bool act = true;
        for (int t = 0; t < HOPS; t++) {
            int e = g_prog[b * HOPS + t];
            act = act && (e != Nn);
            if (act) atomicAdd(&cnt[t][e], 1);
        }
    }
    __syncthreads();
    if (tid < HOPS) {
        int t = tid, p = 0, nt = 0;
        for (int e = 0; e < Nn; e++) {
            cur[t][e] = p;
            int c = cnt[t][e], q = p;
            while (c > 0) {
                g_tileE[t][nt] = e; g_tileS[t][nt] = q;
                g_tileC[t][nt] = (c < 64) ? c : 64;
                q += 64; c -= 64; nt++;
            }
            p += cnt[t][e];
        }
        g_numTiles[t] = nt;
    }
    __syncthreads();
    for (int b = tid; b < Bsz; b += blockDim.x) {
        bool act = true;
        for (int t = 0; t < HOPS; t++) {
            int e = g_prog[b * HOPS + t];
            act = act && (e != Nn);
            if (act) { int p = atomicAdd(&cur[t][e], 1); g_order[t][p] = b; }
        }
    }
}

// ===== copy cur -> next (inactive tokens keep their value; GEMM overwrites actives) =====
__global__ void copy_kernel(int srcSel, int dstSel, float* __restrict__ outbase) {
    const float* s = (srcSel == 0) ? g_z : g_buf;
    float* d = (dstSel == 0) ? g_z : (dstSel == 1) ? g_buf : outbase;
    int i = blockIdx.x * blockDim.x + threadIdx.x;   // exactly B*D/4 threads
    reinterpret_cast<float4*>(d)[i] = reinterpret_cast<const float4*>(s)[i];
}

// ===== grouped gather/scatter GEMM: dst[tok] = gelu(src[tok] @ ops_W[e] + ops_b[e]) =====
__global__ __launch_bounds__(256) void hop_kernel(
    int hop, int srcSel, int dstSel, float* __restrict__ outbase,
    const float* __restrict__ opsW, const float* __restrict__ opsB) {
    if ((int)blockIdx.x >= g_numTiles[hop]) return;
    const float* src = (srcSel == 0) ? g_z : g_buf;
    float* dst = (dstSel == 0) ? g_z : (dstSel == 1) ? g_buf : outbase;
    const int e     = g_tileE[hop][blockIdx.x];
    const int start = g_tileS[hop][blockIdx.x];
    const int cnt   = g_tileC[hop][blockIdx.x];
    const int bn    = blockIdx.y * 64;
    __shared__ int toks[64];
    __shared__ __align__(16) float As[16][68];
    __shared__ __align__(16) float Bs[16][64];
    const int tid  = threadIdx.x;
    const int arow = tid >> 2,  akq = (tid & 3) * 4;
    const int brow = tid >> 4,  bnq = (tid & 15) * 4;
    const int ty   = (tid >> 4) * 4, tx = (tid & 15) * 4;
    if (tid < 64) toks[tid] = (tid < cnt) ? g_order[hop][start + tid] : -1;
    __syncthreads();
    const float* W = opsW + e * (Dm * Dm);
    float acc[4][4] = {};
    const int mytok = toks[arow];
    for (int k0 = 0; k0 < Dm; k0 += 16) {
        float4 av = make_float4(0.f, 0.f, 0.f, 0.f);
        if (mytok >= 0)
            av = *reinterpret_cast<const float4*>(src + mytok * Dm + k0 + akq);
        float4 bv = *reinterpret_cast<const float4*>(W + (k0 + brow) * Dm + bn + bnq);
        As[akq + 0][arow] = av.x; As[akq + 1][arow] = av.y;
        As[akq + 2][arow] = av.z; As[akq + 3][arow] = av.w;
        *reinterpret_cast<float4*>(&Bs[brow][bnq]) = bv;
        __syncthreads();
        MMA16();
        __syncthreads();
    }
#pragma unroll
    for (int i = 0; i < 4; i++) {
        int tk = toks[ty + i];
        if (tk < 0) continue;
#pragma unroll
        for (int j = 0; j < 4; j++)
            dst[tk * Dm + bn + tx + j] =
                gelu_tanh(acc[i][j] + opsB[e * Dm + bn + tx + j]);
    }
}

// =========================== launch ===========================
extern "C" void kernel_launch(void* const* d_in, const int* in_sizes, int n_in,
                              void* d_out, int out_size) {
    const float* x        = (const float*)d_in[0];
    const float* W_in     = (const float*)d_in[1];
    const float* b_in     = (const float*)d_in[2];
    const float* ops_W    = (const float*)d_in[3];
    const float* ops_b    = (const float*)d_in[4];
    const float* sym_W    = (const float*)d_in[5];
    const float* router_W = (const float*)d_in[6];
    const float* router_b = (const float*)d_in[7];
    (void)in_sizes; (void)n_in; (void)out_size;

    float* out   = (float*)d_out;                 // [B, D]
    float* progf = out + Bsz * Dm;                // [B, HOPS] as float
    float* sym   = progf + Bsz * HOPS;            // [B, N, S]

    const int copyBlocks = (Bsz * Dm / 4) / 256;  // 2048

    gemm_z_kernel  <<<dim3(Bsz / 64, Dm / 64), 256>>>(x, W_in, b_in);
    gemm_sym_kernel<<<dim3(Bsz / 64, (Nn * Ss) / 64), 256>>>(sym_W, sym);
    mean_kernel    <<<(Bsz * Ss) / 256, 256>>>(sym);
    router_kernel  <<<Bsz / 8, 288>>>(router_W, router_b, progf);
    schedule_kernel<<<1, 512>>>();

    // hop 0: z -> buf
    copy_kernel<<<copyBlocks, 256>>>(0, 1, out);
    hop_kernel <<<dim3(MAXT, Dm / 64), 256>>>(0, 0, 1, out, ops_W, ops_b);
    // hop 1: buf -> z
    copy_kernel<<<copyBlocks, 256>>>(1, 0, out);
    hop_kernel <<<dim3(MAXT, Dm / 64), 256>>>(1, 1, 0, out, ops_W, ops_b);
    // hop 2: z -> buf
    copy_kernel<<<copyBlocks, 256>>>(0, 1, out);
    hop_kernel <<<dim3(MAXT, Dm / 64), 256>>>(2, 0, 1, out, ops_W, ops_b);
    // hop 3: buf -> d_out (final)
    copy_kernel<<<copyBlocks, 256>>>(1, 2, out);
    hop_kernel <<<dim3(MAXT, Dm / 64), 256>>>(3, 1, 2, out, ops_W, ops_b);
}